// round 1
// baseline (speedup 1.0000x reference)
#include <cuda_runtime.h>
#include <cstdint>
#include <cstdio>

// Problem constants
#define D_MODEL 1024
#define D_INNER 2048
#define NTOK    16384      // B*T = 4*4096
#define T_LEN   4096
#define LN_EPS  1e-5f

// ---------------------------------------------------------------------------
// Scratch (device globals — no allocation allowed)
// ---------------------------------------------------------------------------
__device__ float g_xn[(size_t)NTOK * D_MODEL];        // 64 MB
__device__ float g_xz[(size_t)NTOK * 2 * D_INNER];    // 256 MB
__device__ float g_y [(size_t)NTOK * D_INNER];        // 128 MB

// ---------------------------------------------------------------------------
// LayerNorm: one block per token row (1024 elems), 256 threads, float4
// ---------------------------------------------------------------------------
__global__ void __launch_bounds__(256) ln_kernel(
    const float* __restrict__ x,
    const float* __restrict__ gamma,
    const float* __restrict__ beta,
    float* __restrict__ xn)
{
    __shared__ float red_s[8];
    __shared__ float red_q[8];
    const int row = blockIdx.x;
    const int tid = threadIdx.x;

    const float4 v = reinterpret_cast<const float4*>(x + (size_t)row * D_MODEL)[tid];
    float s = v.x + v.y + v.z + v.w;
    float q = v.x * v.x + v.y * v.y + v.z * v.z + v.w * v.w;

    #pragma unroll
    for (int o = 16; o > 0; o >>= 1) {
        s += __shfl_xor_sync(0xFFFFFFFFu, s, o);
        q += __shfl_xor_sync(0xFFFFFFFFu, q, o);
    }
    if ((tid & 31) == 0) { red_s[tid >> 5] = s; red_q[tid >> 5] = q; }
    __syncthreads();
    if (tid < 32) {
        s = (tid < 8) ? red_s[tid] : 0.0f;
        q = (tid < 8) ? red_q[tid] : 0.0f;
        #pragma unroll
        for (int o = 4; o > 0; o >>= 1) {
            s += __shfl_xor_sync(0xFFFFFFFFu, s, o);
            q += __shfl_xor_sync(0xFFFFFFFFu, q, o);
        }
        if (tid == 0) { red_s[0] = s; red_q[0] = q; }
    }
    __syncthreads();
    const float mu   = red_s[0] * (1.0f / D_MODEL);
    const float var  = red_q[0] * (1.0f / D_MODEL) - mu * mu;
    const float rstd = rsqrtf(var + LN_EPS);

    const float4 g = reinterpret_cast<const float4*>(gamma)[tid];
    const float4 b = reinterpret_cast<const float4*>(beta)[tid];
    float4 o;
    o.x = (v.x - mu) * rstd * g.x + b.x;
    o.y = (v.y - mu) * rstd * g.y + b.y;
    o.z = (v.z - mu) * rstd * g.z + b.z;
    o.w = (v.w - mu) * rstd * g.w + b.w;
    reinterpret_cast<float4*>(xn + (size_t)row * D_MODEL)[tid] = o;
}

// ---------------------------------------------------------------------------
// TF32 tensor-core GEMM:  C[M,N] = A[M,K] * B[N,K]^T  (+ optional residual)
// Tiles: BM=128, BN=128, BK=32; 256 threads (8 warps, 2x4), warp = 64x32.
// cp.async double-buffered, padded smem (stride 36) -> conflict-free LDS.
// ---------------------------------------------------------------------------
#define BM 128
#define BN 128
#define BK 32
#define BKP 36
#define GEMM_SMEM_BYTES (2 * (BM * BKP + BN * BKP) * 4)   // 73728

__device__ __forceinline__ uint32_t cvt_tf32(float f) {
    uint32_t r;
    asm("cvt.rna.tf32.f32 %0, %1;" : "=r"(r) : "f"(f));
    return r;
}

__device__ __forceinline__ void cp_async16(uint32_t smem_addr, const void* gptr) {
    asm volatile("cp.async.cg.shared.global [%0], [%1], 16;\n"
                 :: "r"(smem_addr), "l"(gptr));
}

__device__ __forceinline__ void mma_tf32_16x8x8(float* c, const uint32_t* a, const uint32_t* b) {
    asm volatile(
        "mma.sync.aligned.m16n8k8.row.col.f32.tf32.tf32.f32 "
        "{%0,%1,%2,%3}, {%4,%5,%6,%7}, {%8,%9}, {%0,%1,%2,%3};\n"
        : "+f"(c[0]), "+f"(c[1]), "+f"(c[2]), "+f"(c[3])
        : "r"(a[0]), "r"(a[1]), "r"(a[2]), "r"(a[3]),
          "r"(b[0]), "r"(b[1]));
}

template <bool ADD_RES>
__global__ void __launch_bounds__(256, 2) gemm_tf32_kernel(
    const float* __restrict__ A,   // [M, K] row-major
    const float* __restrict__ Bm,  // [N, K] row-major (used as B^T)
    const float* __restrict__ res, // [M, N] or nullptr
    float* __restrict__ C,         // [M, N]
    int M, int N, int K)
{
    extern __shared__ float smem[];
    const int tid  = threadIdx.x;
    const int warp = tid >> 5;
    const int lane = tid & 31;
    const int wm = (warp & 1) * 64;   // warp row offset inside block tile
    const int wn = (warp >> 1) * 32;  // warp col offset inside block tile
    const int bm = blockIdx.y * BM;
    const int bn = blockIdx.x * BN;

    const int stage_f = BM * BKP + BN * BKP;  // floats per stage

    // async tile loader
    auto load_tiles = [&](int stg, int k0) {
        float* sA = smem + stg * stage_f;
        float* sB = sA + BM * BKP;
        uint32_t aBase = (uint32_t)__cvta_generic_to_shared(sA);
        uint32_t bBase = (uint32_t)__cvta_generic_to_shared(sB);
        int idx = tid;
        #pragma unroll
        for (int i = 0; i < 4; i++, idx += 256) {
            const int r  = idx >> 3;            // 0..127
            const int c4 = (idx & 7) << 2;      // 0,4,...,28
            cp_async16(aBase + (uint32_t)(r * BKP + c4) * 4u,
                       A + (size_t)(bm + r) * K + k0 + c4);
            cp_async16(bBase + (uint32_t)(r * BKP + c4) * 4u,
                       Bm + (size_t)(bn + r) * K + k0 + c4);
        }
        asm volatile("cp.async.commit_group;\n");
    };

    float acc[4][4][4];
    #pragma unroll
    for (int mt = 0; mt < 4; mt++)
        #pragma unroll
        for (int nt = 0; nt < 4; nt++)
            #pragma unroll
            for (int i = 0; i < 4; i++)
                acc[mt][nt][i] = 0.0f;

    const int KT = K / BK;
    load_tiles(0, 0);

    for (int kt = 0; kt < KT; kt++) {
        asm volatile("cp.async.wait_group 0;\n");
        __syncthreads();
        if (kt + 1 < KT) load_tiles((kt + 1) & 1, (kt + 1) * BK);

        const float* sA = smem + (kt & 1) * stage_f;
        const float* sB = sA + BM * BKP;
        const int frow = lane >> 2;   // 0..7
        const int fcol = lane & 3;    // 0..3

        #pragma unroll
        for (int ks = 0; ks < 4; ks++) {
            const int col = ks * 8 + fcol;
            uint32_t af[4][4];
            uint32_t bf[4][2];
            #pragma unroll
            for (int mt = 0; mt < 4; mt++) {
                const float* p = sA + (wm + mt * 16 + frow) * BKP + col;
                af[mt][0] = cvt_tf32(p[0]);
                af[mt][1] = cvt_tf32(p[8 * BKP]);
                af[mt][2] = cvt_tf32(p[4]);
                af[mt][3] = cvt_tf32(p[8 * BKP + 4]);
            }
            #pragma unroll
            for (int nt = 0; nt < 4; nt++) {
                const float* p = sB + (wn + nt * 8 + frow) * BKP + col;
                bf[nt][0] = cvt_tf32(p[0]);
                bf[nt][1] = cvt_tf32(p[4]);
            }
            #pragma unroll
            for (int mt = 0; mt < 4; mt++)
                #pragma unroll
                for (int nt = 0; nt < 4; nt++)
                    mma_tf32_16x8x8(acc[mt][nt], af[mt], bf[nt]);
        }
    }

    // Epilogue
    const int row0 = bm + wm + (lane >> 2);
    const int col0 = bn + wn + 2 * (lane & 3);
    #pragma unroll
    for (int mt = 0; mt < 4; mt++) {
        #pragma unroll
        for (int nt = 0; nt < 4; nt++) {
            const int r  = row0 + mt * 16;
            const int cl = col0 + nt * 8;
            float2 v0 = make_float2(acc[mt][nt][0], acc[mt][nt][1]);
            float2 v1 = make_float2(acc[mt][nt][2], acc[mt][nt][3]);
            if (ADD_RES) {
                const float2 r0 = *reinterpret_cast<const float2*>(res + (size_t)r * N + cl);
                const float2 r1 = *reinterpret_cast<const float2*>(res + (size_t)(r + 8) * N + cl);
                v0.x += r0.x; v0.y += r0.y;
                v1.x += r1.x; v1.y += r1.y;
            }
            *reinterpret_cast<float2*>(C + (size_t)r * N + cl)       = v0;
            *reinterpret_cast<float2*>(C + (size_t)(r + 8) * N + cl) = v1;
        }
    }
}

// ---------------------------------------------------------------------------
// Causal depthwise conv (d_conv=4) + SiLU gating:
//   y[bt,c] = silu(sum_k w[c,k]*x_part[bt+k-3,c] + b[c]) * silu(z[bt,c])
// ---------------------------------------------------------------------------
__device__ __forceinline__ float silu_f(float v) {
    return v / (1.0f + expf(-v));
}

__global__ void __launch_bounds__(256) conv_gate_kernel(
    const float* __restrict__ xz,       // [NTOK, 2*D_INNER]
    const float* __restrict__ conv_w,   // [D_INNER, 1, 4]
    const float* __restrict__ conv_b,   // [D_INNER]
    float* __restrict__ y)              // [NTOK, D_INNER]
{
    const int idx = blockIdx.x * 256 + threadIdx.x;   // < NTOK * D_INNER
    const int c  = idx & (D_INNER - 1);
    const int bt = idx >> 11;                          // / D_INNER
    const int t  = bt & (T_LEN - 1);

    const float4 w4 = reinterpret_cast<const float4*>(conv_w)[c];
    float acc = conv_b[c];
    // k=3 -> current token (always valid)
    acc += w4.w * xz[(size_t)bt * (2 * D_INNER) + c];
    if (t >= 1) acc += w4.z * xz[(size_t)(bt - 1) * (2 * D_INNER) + c];
    if (t >= 2) acc += w4.y * xz[(size_t)(bt - 2) * (2 * D_INNER) + c];
    if (t >= 3) acc += w4.x * xz[(size_t)(bt - 3) * (2 * D_INNER) + c];

    const float z = xz[(size_t)bt * (2 * D_INNER) + D_INNER + c];
    y[(size_t)bt * D_INNER + c] = silu_f(acc) * silu_f(z);
}

// ---------------------------------------------------------------------------
// Launch
// ---------------------------------------------------------------------------
extern "C" void kernel_launch(void* const* d_in, const int* in_sizes, int n_in,
                              void* d_out, int out_size)
{
    const float* x      = (const float*)d_in[0];
    const float* gamma  = (const float*)d_in[1];
    const float* beta   = (const float*)d_in[2];
    const float* W_in   = (const float*)d_in[3];   // [4096, 1024]
    const float* conv_w = (const float*)d_in[4];   // [2048, 1, 4]
    const float* conv_b = (const float*)d_in[5];   // [2048]
    const float* W_out  = (const float*)d_in[6];   // [1024, 2048]
    float* out = (float*)d_out;                    // [NTOK, 1024]

    float *xn, *xz, *y;
    cudaGetSymbolAddress((void**)&xn, g_xn);
    cudaGetSymbolAddress((void**)&xz, g_xz);
    cudaGetSymbolAddress((void**)&y,  g_y);

    cudaFuncSetAttribute(gemm_tf32_kernel<false>,
                         cudaFuncAttributeMaxDynamicSharedMemorySize, GEMM_SMEM_BYTES);
    cudaFuncSetAttribute(gemm_tf32_kernel<true>,
                         cudaFuncAttributeMaxDynamicSharedMemorySize, GEMM_SMEM_BYTES);

    // 1) LayerNorm
    ln_kernel<<<NTOK, 256>>>(x, gamma, beta, xn);

    // 2) in_proj GEMM: xz[16384,4096] = xn[16384,1024] @ W_in[4096,1024]^T
    {
        dim3 grid(2 * D_INNER / BN, NTOK / BM);   // (32, 128)
        gemm_tf32_kernel<false><<<grid, 256, GEMM_SMEM_BYTES>>>(
            xn, W_in, nullptr, xz, NTOK, 2 * D_INNER, D_MODEL);
    }

    // 3) causal depthwise conv + SiLU gate
    {
        const int total = NTOK * D_INNER;
        conv_gate_kernel<<<total / 256, 256>>>(xz, conv_w, conv_b, y);
    }

    // 4) out_proj GEMM + residual: out = x + y[16384,2048] @ W_out[1024,2048]^T
    {
        dim3 grid(D_MODEL / BN, NTOK / BM);       // (8, 128)
        gemm_tf32_kernel<true><<<grid, 256, GEMM_SMEM_BYTES>>>(
            y, W_out, x, out, NTOK, D_MODEL, D_INNER);
    }
}

// round 3
// speedup vs baseline: 1.1093x; 1.1093x over previous
#include <cuda_runtime.h>
#include <cstdint>

// Problem constants
#define D_MODEL 1024
#define D_INNER 2048
#define NTOK    16384      // B*T
#define T_LEN   4096
#define LN_EPS  1e-5f

// ---------------------------------------------------------------------------
// Scratch (device globals — no allocation allowed)
// ---------------------------------------------------------------------------
__device__ float g_xn  [(size_t)NTOK * D_MODEL];          // 64 MB  (tf32-rounded)
__device__ float g_xz  [(size_t)NTOK * 2 * D_INNER];      // 256 MB (fp32)
__device__ float g_y   [(size_t)NTOK * D_INNER];          // 128 MB (tf32-rounded)
__device__ float g_Win [(size_t)2 * D_INNER * D_MODEL];   // 16 MB  (tf32-rounded)
__device__ float g_Wout[(size_t)D_MODEL * D_INNER];       // 8 MB   (tf32-rounded)

// ---------------------------------------------------------------------------
// Helpers
// ---------------------------------------------------------------------------
__device__ __forceinline__ float tf32r(float f) {
    uint32_t r;
    asm("cvt.rna.tf32.f32 %0, %1;" : "=r"(r) : "f"(f));
    return __uint_as_float(r);
}

__device__ __forceinline__ void cp_async16(uint32_t smem_addr, const void* gptr) {
    asm volatile("cp.async.cg.shared.global [%0], [%1], 16;\n"
                 :: "r"(smem_addr), "l"(gptr));
}

__device__ __forceinline__ void mma_tf32_16x8x8(float* c, const uint32_t* a, const uint32_t* b) {
    asm volatile(
        "mma.sync.aligned.m16n8k8.row.col.f32.tf32.tf32.f32 "
        "{%0,%1,%2,%3}, {%4,%5,%6,%7}, {%8,%9}, {%0,%1,%2,%3};\n"
        : "+f"(c[0]), "+f"(c[1]), "+f"(c[2]), "+f"(c[3])
        : "r"(a[0]), "r"(a[1]), "r"(a[2]), "r"(a[3]),
          "r"(b[0]), "r"(b[1]));
}

// ---------------------------------------------------------------------------
// LayerNorm -> tf32-rounded output
// ---------------------------------------------------------------------------
__global__ void __launch_bounds__(256) ln_kernel(
    const float* __restrict__ x, const float* __restrict__ gamma,
    const float* __restrict__ beta, float* __restrict__ xn)
{
    __shared__ float red_s[8];
    __shared__ float red_q[8];
    const int row = blockIdx.x;
    const int tid = threadIdx.x;

    const float4 v = reinterpret_cast<const float4*>(x + (size_t)row * D_MODEL)[tid];
    float s = v.x + v.y + v.z + v.w;
    float q = v.x * v.x + v.y * v.y + v.z * v.z + v.w * v.w;

    #pragma unroll
    for (int o = 16; o > 0; o >>= 1) {
        s += __shfl_xor_sync(0xFFFFFFFFu, s, o);
        q += __shfl_xor_sync(0xFFFFFFFFu, q, o);
    }
    if ((tid & 31) == 0) { red_s[tid >> 5] = s; red_q[tid >> 5] = q; }
    __syncthreads();
    if (tid < 32) {
        s = (tid < 8) ? red_s[tid] : 0.0f;
        q = (tid < 8) ? red_q[tid] : 0.0f;
        #pragma unroll
        for (int o = 4; o > 0; o >>= 1) {
            s += __shfl_xor_sync(0xFFFFFFFFu, s, o);
            q += __shfl_xor_sync(0xFFFFFFFFu, q, o);
        }
        if (tid == 0) { red_s[0] = s; red_q[0] = q; }
    }
    __syncthreads();
    const float mu   = red_s[0] * (1.0f / D_MODEL);
    const float var  = red_q[0] * (1.0f / D_MODEL) - mu * mu;
    const float rstd = rsqrtf(var + LN_EPS);

    const float4 g = reinterpret_cast<const float4*>(gamma)[tid];
    const float4 b = reinterpret_cast<const float4*>(beta)[tid];
    float4 o;
    o.x = tf32r((v.x - mu) * rstd * g.x + b.x);
    o.y = tf32r((v.y - mu) * rstd * g.y + b.y);
    o.z = tf32r((v.z - mu) * rstd * g.z + b.z);
    o.w = tf32r((v.w - mu) * rstd * g.w + b.w);
    reinterpret_cast<float4*>(xn + (size_t)row * D_MODEL)[tid] = o;
}

// ---------------------------------------------------------------------------
// tf32 pre-round (weights)
// ---------------------------------------------------------------------------
__global__ void __launch_bounds__(256) round_kernel(
    const float* __restrict__ in, float* __restrict__ out, int n4)
{
    const int i = blockIdx.x * 256 + threadIdx.x;
    if (i < n4) {
        float4 v = reinterpret_cast<const float4*>(in)[i];
        v.x = tf32r(v.x); v.y = tf32r(v.y); v.z = tf32r(v.z); v.w = tf32r(v.w);
        reinterpret_cast<float4*>(out)[i] = v;
    }
}

// ---------------------------------------------------------------------------
// Causal depthwise conv(4) + SiLU gate -> tf32-rounded y
// ---------------------------------------------------------------------------
__device__ __forceinline__ float silu_f(float v) { return v / (1.0f + expf(-v)); }

__global__ void __launch_bounds__(256) conv_gate_kernel(
    const float* __restrict__ xz, const float* __restrict__ conv_w,
    const float* __restrict__ conv_b, float* __restrict__ y)
{
    const int idx = blockIdx.x * 256 + threadIdx.x;
    const int c  = idx & (D_INNER - 1);
    const int bt = idx >> 11;
    const int t  = bt & (T_LEN - 1);

    const float4 w4 = reinterpret_cast<const float4*>(conv_w)[c];
    float acc = conv_b[c];
    acc += w4.w * xz[(size_t)bt * (2 * D_INNER) + c];
    if (t >= 1) acc += w4.z * xz[(size_t)(bt - 1) * (2 * D_INNER) + c];
    if (t >= 2) acc += w4.y * xz[(size_t)(bt - 2) * (2 * D_INNER) + c];
    if (t >= 3) acc += w4.x * xz[(size_t)(bt - 3) * (2 * D_INNER) + c];

    const float z = xz[(size_t)bt * (2 * D_INNER) + D_INNER + c];
    y[(size_t)bt * D_INNER + c] = tf32r(silu_f(acc) * silu_f(z));
}

// ---------------------------------------------------------------------------
// TF32 tensor-core GEMM (mma.sync, operands pre-rounded to tf32):
//   C[M,N] = A[M,K] * B[N,K]^T  (+ optional residual)
// Tiles: BM=128, BN=128, BK=32; 256 threads (8 warps 2x4), warp = 64x32.
// cp.async double-buffered, padded smem (stride 36) -> conflict-free LDS.
// NO cvt in the mainloop: values already tf32 bit patterns.
// ---------------------------------------------------------------------------
#define BM 128
#define BN 128
#define BK 32
#define BKP 36
#define GEMM_SMEM_BYTES (2 * (BM * BKP + BN * BKP) * 4)   // 73728

template <bool ADD_RES>
__global__ void __launch_bounds__(256, 2) gemm_tf32_kernel(
    const float* __restrict__ A,   // [M, K] row-major, tf32-rounded
    const float* __restrict__ Bm,  // [N, K] row-major, tf32-rounded
    const float* __restrict__ res, // [M, N] or nullptr
    float* __restrict__ C,         // [M, N]
    int M, int N, int K)
{
    extern __shared__ float smem[];
    const int tid  = threadIdx.x;
    const int warp = tid >> 5;
    const int lane = tid & 31;
    const int wm = (warp & 1) * 64;
    const int wn = (warp >> 1) * 32;
    const int bm = blockIdx.y * BM;
    const int bn = blockIdx.x * BN;

    const int stage_f = BM * BKP + BN * BKP;

    auto load_tiles = [&](int stg, int k0) {
        float* sA = smem + stg * stage_f;
        float* sB = sA + BM * BKP;
        uint32_t aBase = (uint32_t)__cvta_generic_to_shared(sA);
        uint32_t bBase = (uint32_t)__cvta_generic_to_shared(sB);
        int idx = tid;
        #pragma unroll
        for (int i = 0; i < 4; i++, idx += 256) {
            const int r  = idx >> 3;
            const int c4 = (idx & 7) << 2;
            cp_async16(aBase + (uint32_t)(r * BKP + c4) * 4u,
                       A + (size_t)(bm + r) * K + k0 + c4);
            cp_async16(bBase + (uint32_t)(r * BKP + c4) * 4u,
                       Bm + (size_t)(bn + r) * K + k0 + c4);
        }
        asm volatile("cp.async.commit_group;\n");
    };

    float acc[4][4][4];
    #pragma unroll
    for (int mt = 0; mt < 4; mt++)
        #pragma unroll
        for (int nt = 0; nt < 4; nt++)
            #pragma unroll
            for (int i = 0; i < 4; i++)
                acc[mt][nt][i] = 0.0f;

    const int KT = K / BK;
    load_tiles(0, 0);

    for (int kt = 0; kt < KT; kt++) {
        asm volatile("cp.async.wait_group 0;\n");
        __syncthreads();
        if (kt + 1 < KT) load_tiles((kt + 1) & 1, (kt + 1) * BK);

        const uint32_t* sA = reinterpret_cast<const uint32_t*>(smem + (kt & 1) * stage_f);
        const uint32_t* sB = sA + BM * BKP;
        const int frow = lane >> 2;
        const int fcol = lane & 3;

        #pragma unroll
        for (int ks = 0; ks < 4; ks++) {
            const int col = ks * 8 + fcol;
            uint32_t af[4][4];
            uint32_t bf[4][2];
            #pragma unroll
            for (int mt = 0; mt < 4; mt++) {
                const uint32_t* p = sA + (wm + mt * 16 + frow) * BKP + col;
                af[mt][0] = p[0];
                af[mt][1] = p[8 * BKP];
                af[mt][2] = p[4];
                af[mt][3] = p[8 * BKP + 4];
            }
            #pragma unroll
            for (int nt = 0; nt < 4; nt++) {
                const uint32_t* p = sB + (wn + nt * 8 + frow) * BKP + col;
                bf[nt][0] = p[0];
                bf[nt][1] = p[4];
            }
            #pragma unroll
            for (int mt = 0; mt < 4; mt++)
                #pragma unroll
                for (int nt = 0; nt < 4; nt++)
                    mma_tf32_16x8x8(acc[mt][nt], af[mt], bf[nt]);
        }
    }

    // Epilogue
    const int row0 = bm + wm + (lane >> 2);
    const int col0 = bn + wn + 2 * (lane & 3);
    #pragma unroll
    for (int mt = 0; mt < 4; mt++) {
        #pragma unroll
        for (int nt = 0; nt < 4; nt++) {
            const int r  = row0 + mt * 16;
            const int cl = col0 + nt * 8;
            float2 v0 = make_float2(acc[mt][nt][0], acc[mt][nt][1]);
            float2 v1 = make_float2(acc[mt][nt][2], acc[mt][nt][3]);
            if (ADD_RES) {
                const float2 r0 = *reinterpret_cast<const float2*>(res + (size_t)r * N + cl);
                const float2 r1 = *reinterpret_cast<const float2*>(res + (size_t)(r + 8) * N + cl);
                v0.x += r0.x; v0.y += r0.y;
                v1.x += r1.x; v1.y += r1.y;
            }
            *reinterpret_cast<float2*>(C + (size_t)r * N + cl)       = v0;
            *reinterpret_cast<float2*>(C + (size_t)(r + 8) * N + cl) = v1;
        }
    }
}

// ---------------------------------------------------------------------------
// Launch
// ---------------------------------------------------------------------------
extern "C" void kernel_launch(void* const* d_in, const int* in_sizes, int n_in,
                              void* d_out, int out_size)
{
    const float* x      = (const float*)d_in[0];
    const float* gamma  = (const float*)d_in[1];
    const float* beta   = (const float*)d_in[2];
    const float* W_in   = (const float*)d_in[3];   // [4096, 1024]
    const float* conv_w = (const float*)d_in[4];   // [2048, 1, 4]
    const float* conv_b = (const float*)d_in[5];   // [2048]
    const float* W_out  = (const float*)d_in[6];   // [1024, 2048]
    float* out = (float*)d_out;                    // [NTOK, 1024]

    float *xn, *xz, *y, *Win, *Wout;
    cudaGetSymbolAddress((void**)&xn,   g_xn);
    cudaGetSymbolAddress((void**)&xz,   g_xz);
    cudaGetSymbolAddress((void**)&y,    g_y);
    cudaGetSymbolAddress((void**)&Win,  g_Win);
    cudaGetSymbolAddress((void**)&Wout, g_Wout);

    cudaFuncSetAttribute(gemm_tf32_kernel<false>,
                         cudaFuncAttributeMaxDynamicSharedMemorySize, GEMM_SMEM_BYTES);
    cudaFuncSetAttribute(gemm_tf32_kernel<true>,
                         cudaFuncAttributeMaxDynamicSharedMemorySize, GEMM_SMEM_BYTES);

    // 0) tf32 pre-round weights (one pass; removes all cvt from GEMM mainloops)
    {
        const int n4_in  = (2 * D_INNER * D_MODEL) / 4;
        const int n4_out = (D_MODEL * D_INNER) / 4;
        round_kernel<<<(n4_in  + 255) / 256, 256>>>(W_in,  Win,  n4_in);
        round_kernel<<<(n4_out + 255) / 256, 256>>>(W_out, Wout, n4_out);
    }

    // 1) LayerNorm (tf32-rounded output)
    ln_kernel<<<NTOK, 256>>>(x, gamma, beta, xn);

    // 2) in_proj GEMM: xz[16384,4096] = xn @ Win^T
    {
        dim3 grid(2 * D_INNER / BN, NTOK / BM);   // (32, 128)
        gemm_tf32_kernel<false><<<grid, 256, GEMM_SMEM_BYTES>>>(
            xn, Win, nullptr, xz, NTOK, 2 * D_INNER, D_MODEL);
    }

    // 3) causal depthwise conv + SiLU gate (tf32-rounded y)
    conv_gate_kernel<<<(NTOK * D_INNER) / 256, 256>>>(xz, conv_w, conv_b, y);

    // 4) out_proj GEMM + residual: out = x + y @ Wout^T
    {
        dim3 grid(D_MODEL / BN, NTOK / BM);       // (8, 128)
        gemm_tf32_kernel<true><<<grid, 256, GEMM_SMEM_BYTES>>>(
            y, Wout, x, out, NTOK, D_MODEL, D_INNER);
    }
}

// round 6
// speedup vs baseline: 2.0340x; 1.8336x over previous
#include <cuda_runtime.h>
#include <cuda_fp16.h>
#include <cstdint>

// Problem constants
#define D_MODEL 1024
#define D_INNER 2048
#define NTOK    16384      // B*T
#define T_LEN   4096
#define LN_EPS  1e-5f

// ---------------------------------------------------------------------------
// Scratch (device globals — no allocation allowed)
// ---------------------------------------------------------------------------
__device__ __half g_xn  [(size_t)NTOK * D_MODEL];          // 32 MB
__device__ __half g_xz  [(size_t)NTOK * 2 * D_INNER];      // 128 MB
__device__ __half g_y   [(size_t)NTOK * D_INNER];          // 64 MB
__device__ __half g_Win [(size_t)2 * D_INNER * D_MODEL];   // 8 MB
__device__ __half g_Wout[(size_t)D_MODEL * D_INNER];       // 4 MB

// ---------------------------------------------------------------------------
// Helpers
// ---------------------------------------------------------------------------
__device__ __forceinline__ void cp_async16(uint32_t smem_addr, const void* gptr) {
    asm volatile("cp.async.cg.shared.global [%0], [%1], 16;\n"
                 :: "r"(smem_addr), "l"(gptr));
}

__device__ __forceinline__ void mma_f16_16x8x16(float* c, const uint32_t* a, const uint32_t* b) {
    asm volatile(
        "mma.sync.aligned.m16n8k16.row.col.f32.f16.f16.f32 "
        "{%0,%1,%2,%3}, {%4,%5,%6,%7}, {%8,%9}, {%0,%1,%2,%3};\n"
        : "+f"(c[0]), "+f"(c[1]), "+f"(c[2]), "+f"(c[3])
        : "r"(a[0]), "r"(a[1]), "r"(a[2]), "r"(a[3]),
          "r"(b[0]), "r"(b[1]));
}

// ---------------------------------------------------------------------------
// LayerNorm -> fp16 output
// ---------------------------------------------------------------------------
__global__ void __launch_bounds__(256) ln_kernel(
    const float* __restrict__ x, const float* __restrict__ gamma,
    const float* __restrict__ beta, __half* __restrict__ xn)
{
    __shared__ float red_s[8];
    __shared__ float red_q[8];
    const int row = blockIdx.x;
    const int tid = threadIdx.x;

    const float4 v = reinterpret_cast<const float4*>(x + (size_t)row * D_MODEL)[tid];
    float s = v.x + v.y + v.z + v.w;
    float q = v.x * v.x + v.y * v.y + v.z * v.z + v.w * v.w;

    #pragma unroll
    for (int o = 16; o > 0; o >>= 1) {
        s += __shfl_xor_sync(0xFFFFFFFFu, s, o);
        q += __shfl_xor_sync(0xFFFFFFFFu, q, o);
    }
    if ((tid & 31) == 0) { red_s[tid >> 5] = s; red_q[tid >> 5] = q; }
    __syncthreads();
    if (tid < 32) {
        s = (tid < 8) ? red_s[tid] : 0.0f;
        q = (tid < 8) ? red_q[tid] : 0.0f;
        #pragma unroll
        for (int o = 4; o > 0; o >>= 1) {
            s += __shfl_xor_sync(0xFFFFFFFFu, s, o);
            q += __shfl_xor_sync(0xFFFFFFFFu, q, o);
        }
        if (tid == 0) { red_s[0] = s; red_q[0] = q; }
    }
    __syncthreads();
    const float mu   = red_s[0] * (1.0f / D_MODEL);
    const float var  = red_q[0] * (1.0f / D_MODEL) - mu * mu;
    const float rstd = rsqrtf(var + LN_EPS);

    const float4 g = reinterpret_cast<const float4*>(gamma)[tid];
    const float4 b = reinterpret_cast<const float4*>(beta)[tid];
    __half2 o0 = __floats2half2_rn((v.x - mu) * rstd * g.x + b.x,
                                   (v.y - mu) * rstd * g.y + b.y);
    __half2 o1 = __floats2half2_rn((v.z - mu) * rstd * g.z + b.z,
                                   (v.w - mu) * rstd * g.w + b.w);
    uint2 pk;
    pk.x = *reinterpret_cast<uint32_t*>(&o0);
    pk.y = *reinterpret_cast<uint32_t*>(&o1);
    reinterpret_cast<uint2*>(xn + (size_t)row * D_MODEL)[tid] = pk;
}

// ---------------------------------------------------------------------------
// fp32 -> fp16 weight conversion
// ---------------------------------------------------------------------------
__global__ void __launch_bounds__(256) cvt_half_kernel(
    const float* __restrict__ in, __half* __restrict__ out, int n4)
{
    const int i = blockIdx.x * 256 + threadIdx.x;
    if (i < n4) {
        const float4 v = reinterpret_cast<const float4*>(in)[i];
        __half2 h0 = __floats2half2_rn(v.x, v.y);
        __half2 h1 = __floats2half2_rn(v.z, v.w);
        uint2 pk;
        pk.x = *reinterpret_cast<uint32_t*>(&h0);
        pk.y = *reinterpret_cast<uint32_t*>(&h1);
        reinterpret_cast<uint2*>(out)[i] = pk;
    }
}

// ---------------------------------------------------------------------------
// Causal depthwise conv(4) + SiLU gate, fp16 in/out, fp32 math, half2 vector
// ---------------------------------------------------------------------------
__device__ __forceinline__ float silu_f(float v) { return v / (1.0f + expf(-v)); }

__global__ void __launch_bounds__(256) conv_gate_kernel(
    const __half* __restrict__ xz, const float* __restrict__ conv_w,
    const float* __restrict__ conv_b, __half* __restrict__ y)
{
    const int idx = blockIdx.x * 256 + threadIdx.x;     // over NTOK*D_INNER/2
    const int c2  = idx & (D_INNER / 2 - 1);            // half2 channel index
    const int bt  = idx >> 10;                          // / (D_INNER/2)
    const int t   = bt & (T_LEN - 1);
    const int c   = c2 * 2;

    const float4 wA = reinterpret_cast<const float4*>(conv_w)[c];
    const float4 wB = reinterpret_cast<const float4*>(conv_w)[c + 1];

    const __half2* xrow = reinterpret_cast<const __half2*>(xz) + (size_t)bt * (2 * D_INNER / 2) + c2;
    const int rs = 2 * D_INNER / 2;   // half2 row stride

    float a0 = conv_b[c], a1 = conv_b[c + 1];
    {
        const float2 v = __half22float2(xrow[0]);
        a0 += wA.w * v.x; a1 += wB.w * v.y;
    }
    if (t >= 1) { const float2 v = __half22float2(xrow[-rs]);     a0 += wA.z * v.x; a1 += wB.z * v.y; }
    if (t >= 2) { const float2 v = __half22float2(xrow[-2 * rs]); a0 += wA.y * v.x; a1 += wB.y * v.y; }
    if (t >= 3) { const float2 v = __half22float2(xrow[-3 * rs]); a0 += wA.x * v.x; a1 += wB.x * v.y; }

    const float2 z = __half22float2(xrow[D_INNER / 2]);
    const float r0 = silu_f(a0) * silu_f(z.x);
    const float r1 = silu_f(a1) * silu_f(z.y);
    reinterpret_cast<__half2*>(y)[(size_t)bt * (D_INNER / 2) + c2] = __floats2half2_rn(r0, r1);
}

// ---------------------------------------------------------------------------
// FP16 tensor-core GEMM (m16n8k16):  C[M,N] = A[M,K] * B[N,K]^T
// Tiles: BM=128, BN=128, BK=64 halves; 256 threads (8 warps 2x4), warp 64x32.
// cp.async double-buffered; smem stride 72 halves -> conflict-free frag LDS.
// ---------------------------------------------------------------------------
#define BM 128
#define BN 128
#define BKH 64
#define BKP 72
#define GEMM_SMEM_BYTES (2 * (BM + BN) * BKP * 2)   // 73728

// OUT_HALF=true: C is half, no residual. OUT_HALF=false: C float, += res.
template <bool OUT_HALF>
__global__ void __launch_bounds__(256, 2) gemm_f16_kernel(
    const __half* __restrict__ A,   // [M, K] row-major
    const __half* __restrict__ Bm,  // [N, K] row-major
    const float* __restrict__ res,  // [M, N] or nullptr
    void* __restrict__ Cp,          // [M, N]
    int M, int N, int K)
{
    extern __shared__ __half smem[];
    const int tid  = threadIdx.x;
    const int warp = tid >> 5;
    const int lane = tid & 31;
    const int wm = (warp & 1) * 64;
    const int wn = (warp >> 1) * 32;
    const int bm = blockIdx.y * BM;
    const int bn = blockIdx.x * BN;

    const int stage_h = (BM + BN) * BKP;   // halves per stage

    auto load_tiles = [&](int stg, int k0) {
        __half* sA = smem + stg * stage_h;
        __half* sB = sA + BM * BKP;
        uint32_t aBase = (uint32_t)__cvta_generic_to_shared(sA);
        uint32_t bBase = (uint32_t)__cvta_generic_to_shared(sB);
        int idx = tid;
        #pragma unroll
        for (int i = 0; i < 4; i++, idx += 256) {       // 1024 chunks of 16B each side
            const int r  = idx >> 3;                    // 0..127
            const int cw = idx & 7;                     // 8-half chunk
            cp_async16(aBase + (uint32_t)(r * BKP + cw * 8) * 2u,
                       A + (size_t)(bm + r) * K + k0 + cw * 8);
            cp_async16(bBase + (uint32_t)(r * BKP + cw * 8) * 2u,
                       Bm + (size_t)(bn + r) * K + k0 + cw * 8);
        }
        asm volatile("cp.async.commit_group;\n");
    };

    float acc[4][4][4];
    #pragma unroll
    for (int mt = 0; mt < 4; mt++)
        #pragma unroll
        for (int nt = 0; nt < 4; nt++)
            #pragma unroll
            for (int i = 0; i < 4; i++)
                acc[mt][nt][i] = 0.0f;

    const int KT = K / BKH;
    load_tiles(0, 0);

    for (int kt = 0; kt < KT; kt++) {
        asm volatile("cp.async.wait_group 0;\n");
        __syncthreads();
        if (kt + 1 < KT) load_tiles((kt + 1) & 1, (kt + 1) * BKH);

        const __half* sA = smem + (kt & 1) * stage_h;
        const __half* sB = sA + BM * BKP;
        const int frow = lane >> 2;        // 0..7
        const int fcol = lane & 3;         // 0..3

        #pragma unroll
        for (int ks = 0; ks < 4; ks++) {   // 4 k-steps of 16
            const int k0 = ks * 16 + 2 * fcol;
            uint32_t af[4][4];
            uint32_t bf[4][2];
            #pragma unroll
            for (int mt = 0; mt < 4; mt++) {
                const __half* p = sA + (wm + mt * 16 + frow) * BKP + k0;
                af[mt][0] = *reinterpret_cast<const uint32_t*>(p);
                af[mt][1] = *reinterpret_cast<const uint32_t*>(p + 8 * BKP);
                af[mt][2] = *reinterpret_cast<const uint32_t*>(p + 8);
                af[mt][3] = *reinterpret_cast<const uint32_t*>(p + 8 * BKP + 8);
            }
            #pragma unroll
            for (int nt = 0; nt < 4; nt++) {
                const __half* p = sB + (wn + nt * 8 + frow) * BKP + k0;
                bf[nt][0] = *reinterpret_cast<const uint32_t*>(p);
                bf[nt][1] = *reinterpret_cast<const uint32_t*>(p + 8);
            }
            #pragma unroll
            for (int mt = 0; mt < 4; mt++)
                #pragma unroll
                for (int nt = 0; nt < 4; nt++)
                    mma_f16_16x8x16(acc[mt][nt], af[mt], bf[nt]);
        }
    }

    // Epilogue
    const int row0 = bm + wm + (lane >> 2);
    const int col0 = bn + wn + 2 * (lane & 3);
    #pragma unroll
    for (int mt = 0; mt < 4; mt++) {
        #pragma unroll
        for (int nt = 0; nt < 4; nt++) {
            const int r  = row0 + mt * 16;
            const int cl = col0 + nt * 8;
            if (OUT_HALF) {
                __half* C = (__half*)Cp;
                *reinterpret_cast<__half2*>(C + (size_t)r * N + cl) =
                    __floats2half2_rn(acc[mt][nt][0], acc[mt][nt][1]);
                *reinterpret_cast<__half2*>(C + (size_t)(r + 8) * N + cl) =
                    __floats2half2_rn(acc[mt][nt][2], acc[mt][nt][3]);
            } else {
                float* C = (float*)Cp;
                const float2 r0 = *reinterpret_cast<const float2*>(res + (size_t)r * N + cl);
                const float2 r1 = *reinterpret_cast<const float2*>(res + (size_t)(r + 8) * N + cl);
                float2 v0 = make_float2(acc[mt][nt][0] + r0.x, acc[mt][nt][1] + r0.y);
                float2 v1 = make_float2(acc[mt][nt][2] + r1.x, acc[mt][nt][3] + r1.y);
                *reinterpret_cast<float2*>(C + (size_t)r * N + cl)       = v0;
                *reinterpret_cast<float2*>(C + (size_t)(r + 8) * N + cl) = v1;
            }
        }
    }
}

// ---------------------------------------------------------------------------
// Launch
// ---------------------------------------------------------------------------
extern "C" void kernel_launch(void* const* d_in, const int* in_sizes, int n_in,
                              void* d_out, int out_size)
{
    const float* x      = (const float*)d_in[0];
    const float* gamma  = (const float*)d_in[1];
    const float* beta   = (const float*)d_in[2];
    const float* W_in   = (const float*)d_in[3];   // [4096, 1024]
    const float* conv_w = (const float*)d_in[4];   // [2048, 1, 4]
    const float* conv_b = (const float*)d_in[5];   // [2048]
    const float* W_out  = (const float*)d_in[6];   // [1024, 2048]
    float* out = (float*)d_out;                    // [NTOK, 1024]

    __half *xn, *xz, *y, *Win, *Wout;
    cudaGetSymbolAddress((void**)&xn,   g_xn);
    cudaGetSymbolAddress((void**)&xz,   g_xz);
    cudaGetSymbolAddress((void**)&y,    g_y);
    cudaGetSymbolAddress((void**)&Win,  g_Win);
    cudaGetSymbolAddress((void**)&Wout, g_Wout);

    cudaFuncSetAttribute(gemm_f16_kernel<true>,
                         cudaFuncAttributeMaxDynamicSharedMemorySize, GEMM_SMEM_BYTES);
    cudaFuncSetAttribute(gemm_f16_kernel<false>,
                         cudaFuncAttributeMaxDynamicSharedMemorySize, GEMM_SMEM_BYTES);

    // 0) fp16 weight conversion (one pass)
    {
        const int n4_in  = (2 * D_INNER * D_MODEL) / 4;
        const int n4_out = (D_MODEL * D_INNER) / 4;
        cvt_half_kernel<<<(n4_in  + 255) / 256, 256>>>(W_in,  Win,  n4_in);
        cvt_half_kernel<<<(n4_out + 255) / 256, 256>>>(W_out, Wout, n4_out);
    }

    // 1) LayerNorm (fp16 output)
    ln_kernel<<<NTOK, 256>>>(x, gamma, beta, xn);

    // 2) in_proj GEMM: xz[16384,4096] (fp16) = xn @ Win^T
    {
        dim3 grid(2 * D_INNER / BN, NTOK / BM);   // (32, 128)
        gemm_f16_kernel<true><<<grid, 256, GEMM_SMEM_BYTES>>>(
            xn, Win, nullptr, xz, NTOK, 2 * D_INNER, D_MODEL);
    }

    // 3) causal depthwise conv + SiLU gate (fp16 y)
    conv_gate_kernel<<<(NTOK * D_INNER / 2) / 256, 256>>>(xz, conv_w, conv_b, y);

    // 4) out_proj GEMM + residual: out = x + y @ Wout^T (fp32 output)
    {
        dim3 grid(D_MODEL / BN, NTOK / BM);       // (8, 128)
        gemm_f16_kernel<false><<<grid, 256, GEMM_SMEM_BYTES>>>(
            y, Wout, x, out, NTOK, D_MODEL, D_INNER);
    }
}

// round 7
// speedup vs baseline: 2.2135x; 1.0882x over previous
#include <cuda_runtime.h>
#include <cuda_fp16.h>
#include <cstdint>

// Problem constants
#define D_MODEL 1024
#define D_INNER 2048
#define NTOK    16384      // B*T
#define T_LEN   4096
#define LN_EPS  1e-5f

// ---------------------------------------------------------------------------
// Scratch (device globals — no allocation allowed)
// ---------------------------------------------------------------------------
__device__ __half g_xn  [(size_t)NTOK * D_MODEL];          // 32 MB
__device__ __half g_xz  [(size_t)NTOK * 2 * D_INNER];      // 128 MB
__device__ __half g_y   [(size_t)NTOK * D_INNER];          // 64 MB
__device__ __half g_Win [(size_t)2 * D_INNER * D_MODEL];   // 8 MB
__device__ __half g_Wout[(size_t)D_MODEL * D_INNER];       // 4 MB

// ---------------------------------------------------------------------------
// Helpers
// ---------------------------------------------------------------------------
__device__ __forceinline__ void cp_async16(uint32_t smem_addr, const void* gptr) {
    asm volatile("cp.async.cg.shared.global [%0], [%1], 16;\n"
                 :: "r"(smem_addr), "l"(gptr));
}

__device__ __forceinline__ void mma_f16_16x8x16(float* c, const uint32_t* a, const uint32_t* b) {
    asm volatile(
        "mma.sync.aligned.m16n8k16.row.col.f32.f16.f16.f32 "
        "{%0,%1,%2,%3}, {%4,%5,%6,%7}, {%8,%9}, {%0,%1,%2,%3};\n"
        : "+f"(c[0]), "+f"(c[1]), "+f"(c[2]), "+f"(c[3])
        : "r"(a[0]), "r"(a[1]), "r"(a[2]), "r"(a[3]),
          "r"(b[0]), "r"(b[1]));
}

__device__ __forceinline__ void ldsm_x4(uint32_t& r0, uint32_t& r1,
                                        uint32_t& r2, uint32_t& r3, uint32_t addr) {
    asm volatile("ldmatrix.sync.aligned.m8n8.x4.shared.b16 {%0,%1,%2,%3}, [%4];"
                 : "=r"(r0), "=r"(r1), "=r"(r2), "=r"(r3) : "r"(addr));
}

// ---------------------------------------------------------------------------
// LayerNorm -> fp16 output
// ---------------------------------------------------------------------------
__global__ void __launch_bounds__(256) ln_kernel(
    const float* __restrict__ x, const float* __restrict__ gamma,
    const float* __restrict__ beta, __half* __restrict__ xn)
{
    __shared__ float red_s[8];
    __shared__ float red_q[8];
    const int row = blockIdx.x;
    const int tid = threadIdx.x;

    const float4 v = reinterpret_cast<const float4*>(x + (size_t)row * D_MODEL)[tid];
    float s = v.x + v.y + v.z + v.w;
    float q = v.x * v.x + v.y * v.y + v.z * v.z + v.w * v.w;

    #pragma unroll
    for (int o = 16; o > 0; o >>= 1) {
        s += __shfl_xor_sync(0xFFFFFFFFu, s, o);
        q += __shfl_xor_sync(0xFFFFFFFFu, q, o);
    }
    if ((tid & 31) == 0) { red_s[tid >> 5] = s; red_q[tid >> 5] = q; }
    __syncthreads();
    if (tid < 32) {
        s = (tid < 8) ? red_s[tid] : 0.0f;
        q = (tid < 8) ? red_q[tid] : 0.0f;
        #pragma unroll
        for (int o = 4; o > 0; o >>= 1) {
            s += __shfl_xor_sync(0xFFFFFFFFu, s, o);
            q += __shfl_xor_sync(0xFFFFFFFFu, q, o);
        }
        if (tid == 0) { red_s[0] = s; red_q[0] = q; }
    }
    __syncthreads();
    const float mu   = red_s[0] * (1.0f / D_MODEL);
    const float var  = red_q[0] * (1.0f / D_MODEL) - mu * mu;
    const float rstd = rsqrtf(var + LN_EPS);

    const float4 g = reinterpret_cast<const float4*>(gamma)[tid];
    const float4 b = reinterpret_cast<const float4*>(beta)[tid];
    __half2 o0 = __floats2half2_rn((v.x - mu) * rstd * g.x + b.x,
                                   (v.y - mu) * rstd * g.y + b.y);
    __half2 o1 = __floats2half2_rn((v.z - mu) * rstd * g.z + b.z,
                                   (v.w - mu) * rstd * g.w + b.w);
    uint2 pk;
    pk.x = *reinterpret_cast<uint32_t*>(&o0);
    pk.y = *reinterpret_cast<uint32_t*>(&o1);
    reinterpret_cast<uint2*>(xn + (size_t)row * D_MODEL)[tid] = pk;
}

// ---------------------------------------------------------------------------
// fp32 -> fp16 weight conversion
// ---------------------------------------------------------------------------
__global__ void __launch_bounds__(256) cvt_half_kernel(
    const float* __restrict__ in, __half* __restrict__ out, int n4)
{
    const int i = blockIdx.x * 256 + threadIdx.x;
    if (i < n4) {
        const float4 v = reinterpret_cast<const float4*>(in)[i];
        __half2 h0 = __floats2half2_rn(v.x, v.y);
        __half2 h1 = __floats2half2_rn(v.z, v.w);
        uint2 pk;
        pk.x = *reinterpret_cast<uint32_t*>(&h0);
        pk.y = *reinterpret_cast<uint32_t*>(&h1);
        reinterpret_cast<uint2*>(out)[i] = pk;
    }
}

// ---------------------------------------------------------------------------
// Causal depthwise conv(4) + SiLU gate, fp16 in/out, fp32 math, half2 vector
// ---------------------------------------------------------------------------
__device__ __forceinline__ float silu_f(float v) { return v / (1.0f + expf(-v)); }

__global__ void __launch_bounds__(256) conv_gate_kernel(
    const __half* __restrict__ xz, const float* __restrict__ conv_w,
    const float* __restrict__ conv_b, __half* __restrict__ y)
{
    const int idx = blockIdx.x * 256 + threadIdx.x;     // over NTOK*D_INNER/2
    const int c2  = idx & (D_INNER / 2 - 1);            // half2 channel index
    const int bt  = idx >> 10;                          // / (D_INNER/2)
    const int t   = bt & (T_LEN - 1);
    const int c   = c2 * 2;

    const float4 wA = reinterpret_cast<const float4*>(conv_w)[c];
    const float4 wB = reinterpret_cast<const float4*>(conv_w)[c + 1];

    const __half2* xrow = reinterpret_cast<const __half2*>(xz) + (size_t)bt * (2 * D_INNER / 2) + c2;
    const int rs = 2 * D_INNER / 2;   // half2 row stride

    float a0 = conv_b[c], a1 = conv_b[c + 1];
    {
        const float2 v = __half22float2(xrow[0]);
        a0 += wA.w * v.x; a1 += wB.w * v.y;
    }
    if (t >= 1) { const float2 v = __half22float2(xrow[-rs]);     a0 += wA.z * v.x; a1 += wB.z * v.y; }
    if (t >= 2) { const float2 v = __half22float2(xrow[-2 * rs]); a0 += wA.y * v.x; a1 += wB.y * v.y; }
    if (t >= 3) { const float2 v = __half22float2(xrow[-3 * rs]); a0 += wA.x * v.x; a1 += wB.x * v.y; }

    const float2 z = __half22float2(xrow[D_INNER / 2]);
    const float r0 = silu_f(a0) * silu_f(z.x);
    const float r1 = silu_f(a1) * silu_f(z.y);
    reinterpret_cast<__half2*>(y)[(size_t)bt * (D_INNER / 2) + c2] = __floats2half2_rn(r0, r1);
}

// ---------------------------------------------------------------------------
// FP16 tensor-core GEMM (m16n8k16 + ldmatrix):  C[M,N] = A[M,K] * B[N,K]^T
// Tiles: BM=128, BN=128, BK=64 halves; 256 threads (8 warps 2x4), warp 64x32.
// cp.async double-buffered; smem stride 72 halves -> LDSM conflict-free
// (row stride 144B = 36 words -> 8 rows hit banks 4i..4i+3, all 32 once).
// ---------------------------------------------------------------------------
#define BM 128
#define BN 128
#define BKH 64
#define BKP 72
#define GEMM_SMEM_BYTES (2 * (BM + BN) * BKP * 2)   // 73728

// OUT_HALF=true: C is half, no residual. OUT_HALF=false: C float, += res.
template <bool OUT_HALF>
__global__ void __launch_bounds__(256, 2) gemm_f16_kernel(
    const __half* __restrict__ A,   // [M, K] row-major
    const __half* __restrict__ Bm,  // [N, K] row-major
    const float* __restrict__ res,  // [M, N] or nullptr
    void* __restrict__ Cp,          // [M, N]
    int M, int N, int K)
{
    extern __shared__ __half smem[];
    const int tid  = threadIdx.x;
    const int warp = tid >> 5;
    const int lane = tid & 31;
    const int wm = (warp & 1) * 64;
    const int wn = (warp >> 1) * 32;
    const int bm = blockIdx.y * BM;
    const int bn = blockIdx.x * BN;

    const int stage_h = (BM + BN) * BKP;   // halves per stage
    const uint32_t smemBase = (uint32_t)__cvta_generic_to_shared(smem);

    // ldmatrix lane offsets (in halves)
    // A x4: m0=rows0-7/k0-7, m1=rows8-15/k0-7, m2=rows0-7/k8-15, m3=rows8-15/k8-15
    const int a_lane = ((lane & 7) + ((lane >> 3) & 1) * 8) * BKP + ((lane >> 4) & 1) * 8;
    // B x4: m0=n0-7/k0-7, m1=n0-7/k8-15, m2=n8-15/k0-7, m3=n8-15/k8-15
    const int b_lane = (((lane >> 4) & 1) * 8 + (lane & 7)) * BKP + ((lane >> 3) & 1) * 8;

    auto load_tiles = [&](int stg, int k0) {
        uint32_t aBase = smemBase + (uint32_t)(stg * stage_h) * 2u;
        uint32_t bBase = aBase + BM * BKP * 2u;
        int idx = tid;
        #pragma unroll
        for (int i = 0; i < 4; i++, idx += 256) {       // 1024 chunks of 16B each side
            const int r  = idx >> 3;                    // 0..127
            const int cw = idx & 7;                     // 8-half chunk
            cp_async16(aBase + (uint32_t)(r * BKP + cw * 8) * 2u,
                       A + (size_t)(bm + r) * K + k0 + cw * 8);
            cp_async16(bBase + (uint32_t)(r * BKP + cw * 8) * 2u,
                       Bm + (size_t)(bn + r) * K + k0 + cw * 8);
        }
        asm volatile("cp.async.commit_group;\n");
    };

    float acc[4][4][4];
    #pragma unroll
    for (int mt = 0; mt < 4; mt++)
        #pragma unroll
        for (int nt = 0; nt < 4; nt++)
            #pragma unroll
            for (int i = 0; i < 4; i++)
                acc[mt][nt][i] = 0.0f;

    const int KT = K / BKH;
    load_tiles(0, 0);

    for (int kt = 0; kt < KT; kt++) {
        asm volatile("cp.async.wait_group 0;\n");
        __syncthreads();
        if (kt + 1 < KT) load_tiles((kt + 1) & 1, (kt + 1) * BKH);

        const uint32_t sAaddr = smemBase + (uint32_t)((kt & 1) * stage_h) * 2u;
        const uint32_t sBaddr = sAaddr + BM * BKP * 2u;

        #pragma unroll
        for (int ks = 0; ks < 4; ks++) {   // 4 k-steps of 16
            const int k0 = ks * 16;
            uint32_t af[4][4];
            uint32_t bf[4][2];
            #pragma unroll
            for (int mt = 0; mt < 4; mt++) {
                ldsm_x4(af[mt][0], af[mt][1], af[mt][2], af[mt][3],
                        sAaddr + (uint32_t)(((wm + mt * 16) * BKP + k0 + a_lane) * 2));
            }
            #pragma unroll
            for (int ntp = 0; ntp < 2; ntp++) {
                ldsm_x4(bf[2 * ntp][0], bf[2 * ntp][1], bf[2 * ntp + 1][0], bf[2 * ntp + 1][1],
                        sBaddr + (uint32_t)(((wn + ntp * 16) * BKP + k0 + b_lane) * 2));
            }
            #pragma unroll
            for (int mt = 0; mt < 4; mt++)
                #pragma unroll
                for (int nt = 0; nt < 4; nt++)
                    mma_f16_16x8x16(acc[mt][nt], af[mt], bf[nt]);
        }
    }

    // Epilogue
    const int row0 = bm + wm + (lane >> 2);
    const int col0 = bn + wn + 2 * (lane & 3);
    #pragma unroll
    for (int mt = 0; mt < 4; mt++) {
        #pragma unroll
        for (int nt = 0; nt < 4; nt++) {
            const int r  = row0 + mt * 16;
            const int cl = col0 + nt * 8;
            if (OUT_HALF) {
                __half* C = (__half*)Cp;
                *reinterpret_cast<__half2*>(C + (size_t)r * N + cl) =
                    __floats2half2_rn(acc[mt][nt][0], acc[mt][nt][1]);
                *reinterpret_cast<__half2*>(C + (size_t)(r + 8) * N + cl) =
                    __floats2half2_rn(acc[mt][nt][2], acc[mt][nt][3]);
            } else {
                float* C = (float*)Cp;
                const float2 r0 = *reinterpret_cast<const float2*>(res + (size_t)r * N + cl);
                const float2 r1 = *reinterpret_cast<const float2*>(res + (size_t)(r + 8) * N + cl);
                float2 v0 = make_float2(acc[mt][nt][0] + r0.x, acc[mt][nt][1] + r0.y);
                float2 v1 = make_float2(acc[mt][nt][2] + r1.x, acc[mt][nt][3] + r1.y);
                *reinterpret_cast<float2*>(C + (size_t)r * N + cl)       = v0;
                *reinterpret_cast<float2*>(C + (size_t)(r + 8) * N + cl) = v1;
            }
        }
    }
}

// ---------------------------------------------------------------------------
// Launch
// ---------------------------------------------------------------------------
extern "C" void kernel_launch(void* const* d_in, const int* in_sizes, int n_in,
                              void* d_out, int out_size)
{
    const float* x      = (const float*)d_in[0];
    const float* gamma  = (const float*)d_in[1];
    const float* beta   = (const float*)d_in[2];
    const float* W_in   = (const float*)d_in[3];   // [4096, 1024]
    const float* conv_w = (const float*)d_in[4];   // [2048, 1, 4]
    const float* conv_b = (const float*)d_in[5];   // [2048]
    const float* W_out  = (const float*)d_in[6];   // [1024, 2048]
    float* out = (float*)d_out;                    // [NTOK, 1024]

    __half *xn, *xz, *y, *Win, *Wout;
    cudaGetSymbolAddress((void**)&xn,   g_xn);
    cudaGetSymbolAddress((void**)&xz,   g_xz);
    cudaGetSymbolAddress((void**)&y,    g_y);
    cudaGetSymbolAddress((void**)&Win,  g_Win);
    cudaGetSymbolAddress((void**)&Wout, g_Wout);

    cudaFuncSetAttribute(gemm_f16_kernel<true>,
                         cudaFuncAttributeMaxDynamicSharedMemorySize, GEMM_SMEM_BYTES);
    cudaFuncSetAttribute(gemm_f16_kernel<false>,
                         cudaFuncAttributeMaxDynamicSharedMemorySize, GEMM_SMEM_BYTES);

    // 0) fp16 weight conversion (one pass)
    {
        const int n4_in  = (2 * D_INNER * D_MODEL) / 4;
        const int n4_out = (D_MODEL * D_INNER) / 4;
        cvt_half_kernel<<<(n4_in  + 255) / 256, 256>>>(W_in,  Win,  n4_in);
        cvt_half_kernel<<<(n4_out + 255) / 256, 256>>>(W_out, Wout, n4_out);
    }

    // 1) LayerNorm (fp16 output)
    ln_kernel<<<NTOK, 256>>>(x, gamma, beta, xn);

    // 2) in_proj GEMM: xz[16384,4096] (fp16) = xn @ Win^T
    {
        dim3 grid(2 * D_INNER / BN, NTOK / BM);   // (32, 128)
        gemm_f16_kernel<true><<<grid, 256, GEMM_SMEM_BYTES>>>(
            xn, Win, nullptr, xz, NTOK, 2 * D_INNER, D_MODEL);
    }

    // 3) causal depthwise conv + SiLU gate (fp16 y)
    conv_gate_kernel<<<(NTOK * D_INNER / 2) / 256, 256>>>(xz, conv_w, conv_b, y);

    // 4) out_proj GEMM + residual: out = x + y @ Wout^T (fp32 output)
    {
        dim3 grid(D_MODEL / BN, NTOK / BM);       // (8, 128)
        gemm_f16_kernel<false><<<grid, 256, GEMM_SMEM_BYTES>>>(
            y, Wout, x, out, NTOK, D_MODEL, D_INNER);
    }
}